// round 2
// baseline (speedup 1.0000x reference)
#include <cuda_runtime.h>
#include <math.h>
#include <stdint.h>

#define S    4096
#define DM   1024
#define DI   2048
#define NST  16
#define RB   96     // DT_RANK + 2*D_STATE = 64 + 32
#define SPLITK 8

// ---------------- scratch (device globals; no runtime allocation) ----------
__device__ float g_enc[S * DM];
__device__ float g_h[S * DM];
__device__ float g_xz[S * 2 * DI];
__device__ float g_u[S * DI];
__device__ float g_dbc[S * RB];
__device__ float g_delta[S * DI];
__device__ float g_y[S * DI];
__device__ float g_gated[S * DI];
__device__ float g_split[SPLITK * S * RB];

// ---------------- block reduction helper (256 threads) ---------------------
__device__ __forceinline__ float block_sum(float v, float* red) {
#pragma unroll
    for (int o = 16; o; o >>= 1) v += __shfl_xor_sync(0xffffffffu, v, o);
    if ((threadIdx.x & 31) == 0) red[threadIdx.x >> 5] = v;
    __syncthreads();
    float t = red[0] + red[1] + red[2] + red[3] + red[4] + red[5] + red[6] + red[7];
    __syncthreads();
    return t;
}

// ---------------- LayerNorm (optionally fused add), W in {1024, 2048} ------
__global__ void ln_kernel(const float* __restrict__ src,
                          const float* __restrict__ add,
                          const float* __restrict__ gam,
                          const float* __restrict__ bet,
                          float* __restrict__ out, int W, float eps) {
    __shared__ float red[8];
    const int r = blockIdx.x;
    const int nloc = W >> 8;
    float vals[8];
    float s = 0.f;
    for (int j = 0; j < nloc; j++) {
        int i = threadIdx.x + (j << 8);
        float v = src[(size_t)r * W + i];
        if (add) v += add[(size_t)r * W + i];
        vals[j] = v;
        s += v;
    }
    float mean = block_sum(s, red) / (float)W;
    float s2 = 0.f;
    for (int j = 0; j < nloc; j++) {
        float d = vals[j] - mean;
        s2 += d * d;
    }
    float rstd = rsqrtf(block_sum(s2, red) / (float)W + eps);
    for (int j = 0; j < nloc; j++) {
        int i = threadIdx.x + (j << 8);
        out[(size_t)r * W + i] = (vals[j] - mean) * rstd * gam[i] + bet[i];
    }
}

// ---------------- LN(y) * silu(z) (W = 2048), z = xz[:, 2048:] -------------
__global__ void ln_gate_kernel(const float* __restrict__ y,
                               const float* __restrict__ xz,
                               const float* __restrict__ gam,
                               const float* __restrict__ bet,
                               float* __restrict__ out) {
    __shared__ float red[8];
    const int r = blockIdx.x;
    float vals[8];
    float s = 0.f;
#pragma unroll
    for (int j = 0; j < 8; j++) {
        int i = threadIdx.x + (j << 8);
        float v = y[(size_t)r * DI + i];
        vals[j] = v;
        s += v;
    }
    float mean = block_sum(s, red) / (float)DI;
    float s2 = 0.f;
#pragma unroll
    for (int j = 0; j < 8; j++) {
        float d = vals[j] - mean;
        s2 += d * d;
    }
    float rstd = rsqrtf(block_sum(s2, red) / (float)DI + 1e-5f);
#pragma unroll
    for (int j = 0; j < 8; j++) {
        int i = threadIdx.x + (j << 8);
        float z = xz[(size_t)r * (2 * DI) + DI + i];
        float sz = z / (1.f + expf(-z));
        out[(size_t)r * DI + i] = ((vals[j] - mean) * rstd * gam[i] + bet[i]) * sz;
    }
}

// ---------------- depthwise conv1d k=3 pad=1 over x1 = xz[:, :2048] --------
__global__ void conv_kernel(const float* __restrict__ xz,
                            const float* __restrict__ w,
                            const float* __restrict__ b,
                            float* __restrict__ u) {
    int idx = blockIdx.x * blockDim.x + threadIdx.x;
    int c = idx & (DI - 1);
    int s = idx >> 11;
    float w0 = w[c * 3 + 0], w1 = w[c * 3 + 1], w2 = w[c * 3 + 2];
    float acc = b[c] + w1 * xz[(size_t)s * (2 * DI) + c];
    if (s > 0)     acc += w0 * xz[(size_t)(s - 1) * (2 * DI) + c];
    if (s < S - 1) acc += w2 * xz[(size_t)(s + 1) * (2 * DI) + c];
    u[(size_t)s * DI + c] = acc;
}

// ---------------- split-K reduction for deltaBC ----------------------------
__global__ void reduce_split_kernel(const float* __restrict__ part,
                                    float* __restrict__ out) {
    int i = blockIdx.x * blockDim.x + threadIdx.x;   // S*RB threads
    float s = 0.f;
#pragma unroll
    for (int z = 0; z < SPLITK; z++) s += part[(size_t)z * S * RB + i];
    out[i] = s;
}

// ---------------- tf32 helpers ---------------------------------------------
__device__ __forceinline__ uint32_t f2tf(float v) {
    uint32_t r;
    asm("cvt.rna.tf32.f32 %0, %1;" : "=r"(r) : "f"(v));
    return r;
}

__device__ __forceinline__ void mma_tf32(float* d, const uint32_t* a, const uint32_t* b) {
    asm volatile(
        "mma.sync.aligned.m16n8k8.row.col.f32.tf32.tf32.f32 "
        "{%0,%1,%2,%3},{%4,%5,%6,%7},{%8,%9},{%0,%1,%2,%3};\n"
        : "+f"(d[0]), "+f"(d[1]), "+f"(d[2]), "+f"(d[3])
        : "r"(a[0]), "r"(a[1]), "r"(a[2]), "r"(a[3]), "r"(b[0]), "r"(b[1]));
}

// ---------------- TF32 3x GEMM NT: C[M,N] = A[M,K] * B[N,K]^T --------------
// 128x128x32 tile, 256 threads (8 warps, 2x4), warp tile 64x32 (4x4 atoms).
// hi/lo tf32 split stored interleaved as float2 in smem, XOR swizzle.
// Optional split-K: gridDim.z > 1, each z does kLen, writes C + z*zstride.
__global__ __launch_bounds__(256)
void gemm_tf32(const float* __restrict__ A, int lda,
               const float* __restrict__ B, int ldb,   // ldb == K stride of B rows
               const float* __restrict__ bias,
               const float* __restrict__ skip,
               float* __restrict__ C, int ldc,
               int N, int act, int kLen, size_t zstride) {
    extern __shared__ char smem_raw[];
    float2* As = (float2*)smem_raw;                 // [32][128]
    float2* Bs = (float2*)(smem_raw + 32 * 128 * 8);

    const int tid  = threadIdx.x;
    const int lane = tid & 31;
    const int warp = tid >> 5;
    const int g = lane >> 2;
    const int t = lane & 3;
    const int m0w = (warp >> 2) * 64;
    const int n0w = (warp & 3) * 32;
    const int bm = blockIdx.y * 128;
    const int bn = blockIdx.x * 128;
    const int kStart = blockIdx.z * kLen;
    float* Cz = C + (size_t)blockIdx.z * zstride;

    const int r0 = tid >> 2;      // 0..63
    const int f  = tid & 3;

    float acc[4][4][4];
#pragma unroll
    for (int i = 0; i < 4; i++)
#pragma unroll
        for (int j = 0; j < 4; j++)
#pragma unroll
            for (int k = 0; k < 4; k++) acc[i][j][k] = 0.f;

    for (int k0 = kStart; k0 < kStart + kLen; k0 += 32) {
        // ---- load + convert tile to smem ----
        __syncthreads();
#pragma unroll
        for (int half = 0; half < 2; half++) {
            int r = r0 + half * 64;
#pragma unroll
            for (int fh = 0; fh < 2; fh++) {
                int k4 = (f + fh * 4) * 4;           // 0..28, k4&3==0, (k4+j)&3==j
                // A tile
                float4 av = *(const float4*)(A + (size_t)(bm + r) * lda + k0 + k4);
                // B tile (rows may exceed N)
                int nrow = bn + r;
                float4 bv = (nrow < N) ? *(const float4*)(B + (size_t)nrow * ldb + k0 + k4)
                                       : make_float4(0.f, 0.f, 0.f, 0.f);
                float a4[4] = {av.x, av.y, av.z, av.w};
                float b4[4] = {bv.x, bv.y, bv.z, bv.w};
#pragma unroll
                for (int j = 0; j < 4; j++) {
                    int k = k4 + j;
                    int sw = r ^ (j << 2);
                    uint32_t ahi = f2tf(a4[j]);
                    uint32_t alo = f2tf(a4[j] - __uint_as_float(ahi));
                    As[k * 128 + sw] = make_float2(__uint_as_float(ahi), __uint_as_float(alo));
                    uint32_t bhi = f2tf(b4[j]);
                    uint32_t blo = f2tf(b4[j] - __uint_as_float(bhi));
                    Bs[k * 128 + sw] = make_float2(__uint_as_float(bhi), __uint_as_float(blo));
                }
            }
        }
        __syncthreads();

        // ---- compute: 4 k-atoms of 8 ----
#pragma unroll
        for (int ka = 0; ka < 4; ka++) {
            int kb = ka * 8;
            float2 af[4][4];
            float2 bf[4][2];
            int sw = t << 2;
#pragma unroll
            for (int am = 0; am < 4; am++) {
                int m = m0w + am * 16;
                af[am][0] = As[(kb + t) * 128 + ((m + g) ^ sw)];
                af[am][1] = As[(kb + t) * 128 + ((m + g + 8) ^ sw)];
                af[am][2] = As[(kb + t + 4) * 128 + ((m + g) ^ sw)];
                af[am][3] = As[(kb + t + 4) * 128 + ((m + g + 8) ^ sw)];
            }
#pragma unroll
            for (int an = 0; an < 4; an++) {
                int n = n0w + an * 8;
                bf[an][0] = Bs[(kb + t) * 128 + ((n + g) ^ sw)];
                bf[an][1] = Bs[(kb + t + 4) * 128 + ((n + g) ^ sw)];
            }
#pragma unroll
            for (int am = 0; am < 4; am++) {
                uint32_t ahi[4] = {__float_as_uint(af[am][0].x), __float_as_uint(af[am][1].x),
                                   __float_as_uint(af[am][2].x), __float_as_uint(af[am][3].x)};
                uint32_t alo[4] = {__float_as_uint(af[am][0].y), __float_as_uint(af[am][1].y),
                                   __float_as_uint(af[am][2].y), __float_as_uint(af[am][3].y)};
#pragma unroll
                for (int an = 0; an < 4; an++) {
                    uint32_t bhi[2] = {__float_as_uint(bf[an][0].x), __float_as_uint(bf[an][1].x)};
                    uint32_t blo[2] = {__float_as_uint(bf[an][0].y), __float_as_uint(bf[an][1].y)};
                    mma_tf32(acc[am][an], ahi, bhi);
                    mma_tf32(acc[am][an], ahi, blo);
                    mma_tf32(acc[am][an], alo, bhi);
                }
            }
        }
    }

    // ---- epilogue ----
#pragma unroll
    for (int am = 0; am < 4; am++) {
        int row0 = bm + m0w + am * 16 + g;
        int row1 = row0 + 8;
#pragma unroll
        for (int an = 0; an < 4; an++) {
            int col = bn + n0w + an * 8 + 2 * t;
            if (col < N) {
                float v0 = acc[am][an][0];
                float v1 = acc[am][an][1];
                float v2 = acc[am][an][2];
                float v3 = acc[am][an][3];
                if (bias) { v0 += bias[col]; v1 += bias[col + 1]; v2 += bias[col]; v3 += bias[col + 1]; }
                if (skip) {
                    v0 += skip[(size_t)row0 * ldc + col];
                    v1 += skip[(size_t)row0 * ldc + col + 1];
                    v2 += skip[(size_t)row1 * ldc + col];
                    v3 += skip[(size_t)row1 * ldc + col + 1];
                }
                if (act == 1) {
                    v0 = (v0 > 20.f) ? v0 : log1pf(expf(v0));
                    v1 = (v1 > 20.f) ? v1 : log1pf(expf(v1));
                    v2 = (v2 > 20.f) ? v2 : log1pf(expf(v2));
                    v3 = (v3 > 20.f) ? v3 : log1pf(expf(v3));
                }
                *(float2*)(Cz + (size_t)row0 * ldc + col) = make_float2(v0, v1);
                *(float2*)(Cz + (size_t)row1 * ldc + col) = make_float2(v2, v3);
            }
        }
    }
}

// ---------------- selective scan: 16 lanes per d-channel -------------------
__global__ void scan_kernel(const float* __restrict__ u,
                            const float* __restrict__ delta,
                            const float* __restrict__ dbc,
                            const float* __restrict__ A_log,
                            const float* __restrict__ Dp,
                            float* __restrict__ y) {
    const int tid = threadIdx.x;
    const int nlane = tid & 15;
    const int dloc = tid >> 4;
    const int d = blockIdx.x * 16 + dloc;
    const float A = -__expf(A_log[d * NST + nlane]);
    const float Dv = Dp[d];
    float h = 0.f;
    for (int t = 0; t < S; t++) {
        float dt = delta[(size_t)t * DI + d];
        float uu = u[(size_t)t * DI + d];
        float Bn = dbc[(size_t)t * RB + 64 + nlane];
        float Cn = dbc[(size_t)t * RB + 80 + nlane];
        float dA = __expf(dt * A);
        h = dA * h + (dt * uu) * Bn;
        float p = h * Cn;
        p += __shfl_xor_sync(0xffffffffu, p, 1);
        p += __shfl_xor_sync(0xffffffffu, p, 2);
        p += __shfl_xor_sync(0xffffffffu, p, 4);
        p += __shfl_xor_sync(0xffffffffu, p, 8);
        if (nlane == 0) y[(size_t)t * DI + d] = p + Dv * uu;
    }
}

// ---------------- launcher --------------------------------------------------
extern "C" void kernel_launch(void* const* d_in, const int* in_sizes, int n_in,
                              void* d_out, int out_size) {
    const float* x         = (const float*)d_in[0];
    const float* pos_enc   = (const float*)d_in[1];
    const float* ln_g      = (const float*)d_in[2];
    const float* ln_b      = (const float*)d_in[3];
    const float* innorm_g  = (const float*)d_in[4];
    const float* innorm_b  = (const float*)d_in[5];
    const float* in_proj_w = (const float*)d_in[6];
    const float* in_proj_b = (const float*)d_in[7];
    const float* conv_w    = (const float*)d_in[8];
    const float* conv_b    = (const float*)d_in[9];
    const float* deltaBC_w = (const float*)d_in[10];
    const float* dt_proj_w = (const float*)d_in[11];
    const float* dt_proj_b = (const float*)d_in[12];
    const float* A_log     = (const float*)d_in[13];
    const float* Dp        = (const float*)d_in[14];
    const float* outnorm_g = (const float*)d_in[15];
    const float* outnorm_b = (const float*)d_in[16];
    const float* out_proj_w= (const float*)d_in[17];
    const float* out_proj_b= (const float*)d_in[18];

    float *enc, *h, *xz, *u, *dbc, *delta, *y, *gated, *split;
    cudaGetSymbolAddress((void**)&enc,   g_enc);
    cudaGetSymbolAddress((void**)&h,     g_h);
    cudaGetSymbolAddress((void**)&xz,    g_xz);
    cudaGetSymbolAddress((void**)&u,     g_u);
    cudaGetSymbolAddress((void**)&dbc,   g_dbc);
    cudaGetSymbolAddress((void**)&delta, g_delta);
    cudaGetSymbolAddress((void**)&y,     g_y);
    cudaGetSymbolAddress((void**)&gated, g_gated);
    cudaGetSymbolAddress((void**)&split, g_split);

    const int SMEM = 64 * 1024;
    static int attr_done = 0;
    if (!attr_done) {
        cudaFuncSetAttribute(gemm_tf32, cudaFuncAttributeMaxDynamicSharedMemorySize, SMEM);
        attr_done = 1;
    }

    // enc = LN(x + pos_enc), eps=1e-6
    ln_kernel<<<S, 256>>>(x, pos_enc, ln_g, ln_b, enc, DM, 1e-6f);

    for (int i = 0; i < 4; i++) {
        // h = LN(enc), eps=1e-5
        ln_kernel<<<S, 256>>>(enc, nullptr, innorm_g + i * DM, innorm_b + i * DM,
                              h, DM, 1e-5f);
        // xz = h @ in_proj_w^T + b   [4096, 4096] K=1024
        gemm_tf32<<<dim3(32, 32, 1), 256, SMEM>>>(
            h, DM, in_proj_w + (size_t)i * 2 * DI * DM, DM,
            in_proj_b + (size_t)i * 2 * DI, nullptr,
            xz, 2 * DI, 2 * DI, 0, DM, 0);
        // u = depthwise conv(x1) + b
        conv_kernel<<<(S * DI) / 256, 256>>>(xz, conv_w + (size_t)i * DI * 3,
                                             conv_b + (size_t)i * DI, u);
        // dbc = u @ deltaBC_w^T  [4096, 96] K=2048, split-K=8
        gemm_tf32<<<dim3(1, 32, SPLITK), 256, SMEM>>>(
            u, DI, deltaBC_w + (size_t)i * RB * DI, DI,
            nullptr, nullptr, split, RB, RB, 0, DI / SPLITK, (size_t)S * RB);
        reduce_split_kernel<<<(S * RB) / 256, 256>>>(split, dbc);
        // delta = softplus(dbc[:, :64] @ dt_proj_w^T + b)   [4096, 2048] K=64
        gemm_tf32<<<dim3(16, 32, 1), 256, SMEM>>>(
            dbc, RB, dt_proj_w + (size_t)i * DI * 64, 64,
            dt_proj_b + (size_t)i * DI, nullptr,
            delta, DI, DI, 1, 64, 0);
        // selective scan -> y (incl. + u*D)
        scan_kernel<<<DI / 16, 256>>>(u, delta, dbc,
                                      A_log + (size_t)i * DI * NST,
                                      Dp + (size_t)i * DI, y);
        // gated = LN(y) * silu(z1)
        ln_gate_kernel<<<S, 256>>>(y, xz, outnorm_g + (size_t)i * DI,
                                   outnorm_b + (size_t)i * DI, gated);
        // enc = gated @ out_proj_w^T + b + enc(skip)   [4096, 1024] K=2048
        float* dest = (i == 3) ? (float*)d_out : enc;
        gemm_tf32<<<dim3(8, 32, 1), 256, SMEM>>>(
            gated, DI, out_proj_w + (size_t)i * DM * DI, DI,
            out_proj_b + (size_t)i * DM, enc,
            dest, DM, DM, 0, DI, 0);
    }
}

// round 4
// speedup vs baseline: 1.6858x; 1.6858x over previous
#include <cuda_runtime.h>
#include <cuda_bf16.h>
#include <math.h>
#include <stdint.h>

#define S    4096
#define DM   1024
#define DI   2048
#define NST  16
#define RB   96
#define SPLITK 4

// ---------------- scratch (device globals) ---------------------------------
__device__ float g_enc[S * DM];
__device__ float g_h[S * DM];
__device__ float g_xz[S * 2 * DI];
__device__ float g_u[S * DI];
__device__ float g_dbc[S * RB];
__device__ float g_delta[S * DI];
__device__ float g_y[S * DI];
__device__ float g_gated[S * DI];
__device__ float g_split[SPLITK * S * RB];
__device__ __nv_bfloat16 g_ahi[S * DI];
__device__ __nv_bfloat16 g_alo[S * DI];
__device__ __nv_bfloat16 g_bhi[2 * DI * DM];
__device__ __nv_bfloat16 g_blo[2 * DI * DM];

// ---------------- PTX helpers ----------------------------------------------
__device__ __forceinline__ void mma_bf16(float* d, const uint32_t* a, const uint32_t* b) {
    asm volatile("mma.sync.aligned.m16n8k16.row.col.f32.bf16.bf16.f32 "
        "{%0,%1,%2,%3},{%4,%5,%6,%7},{%8,%9},{%0,%1,%2,%3};"
        : "+f"(d[0]), "+f"(d[1]), "+f"(d[2]), "+f"(d[3])
        : "r"(a[0]), "r"(a[1]), "r"(a[2]), "r"(a[3]), "r"(b[0]), "r"(b[1]));
}
__device__ __forceinline__ void ldsm_x4(uint32_t* r, uint32_t addr) {
    asm volatile("ldmatrix.sync.aligned.m8n8.x4.shared.b16 {%0,%1,%2,%3}, [%4];"
        : "=r"(r[0]), "=r"(r[1]), "=r"(r[2]), "=r"(r[3]) : "r"(addr));
}
__device__ __forceinline__ void ldsm_x2(uint32_t* r, uint32_t addr) {
    asm volatile("ldmatrix.sync.aligned.m8n8.x2.shared.b16 {%0,%1}, [%2];"
        : "=r"(r[0]), "=r"(r[1]) : "r"(addr));
}
#define CP_ASYNC16(dst, src, sz) \
    asm volatile("cp.async.cg.shared.global [%0], [%1], 16, %2;" \
                 :: "r"(dst), "l"(src), "r"(sz) : "memory")
#define CP_COMMIT() asm volatile("cp.async.commit_group;" ::: "memory")
#define CP_WAIT(n)  asm volatile("cp.async.wait_group %0;" :: "n"(n) : "memory")

// ---------------- block reduction helper ------------------------------------
__device__ __forceinline__ float block_sum(float v, float* red) {
#pragma unroll
    for (int o = 16; o; o >>= 1) v += __shfl_xor_sync(0xffffffffu, v, o);
    if ((threadIdx.x & 31) == 0) red[threadIdx.x >> 5] = v;
    __syncthreads();
    float t = red[0] + red[1] + red[2] + red[3] + red[4] + red[5] + red[6] + red[7];
    __syncthreads();
    return t;
}

// ---------------- LayerNorm --------------------------------------------------
__global__ void ln_kernel(const float* __restrict__ src, const float* __restrict__ add,
                          const float* __restrict__ gam, const float* __restrict__ bet,
                          float* __restrict__ out, int W, float eps) {
    __shared__ float red[8];
    const int r = blockIdx.x;
    const int nloc = W >> 8;
    float vals[8];
    float s = 0.f;
    for (int j = 0; j < nloc; j++) {
        int i = threadIdx.x + (j << 8);
        float v = src[(size_t)r * W + i];
        if (add) v += add[(size_t)r * W + i];
        vals[j] = v;
        s += v;
    }
    float mean = block_sum(s, red) / (float)W;
    float s2 = 0.f;
    for (int j = 0; j < nloc; j++) { float d = vals[j] - mean; s2 += d * d; }
    float rstd = rsqrtf(block_sum(s2, red) / (float)W + eps);
    for (int j = 0; j < nloc; j++) {
        int i = threadIdx.x + (j << 8);
        out[(size_t)r * W + i] = (vals[j] - mean) * rstd * gam[i] + bet[i];
    }
}

// ---------------- LN(y) * silu(z) -------------------------------------------
__global__ void ln_gate_kernel(const float* __restrict__ y, const float* __restrict__ xz,
                               const float* __restrict__ gam, const float* __restrict__ bet,
                               float* __restrict__ out) {
    __shared__ float red[8];
    const int r = blockIdx.x;
    float vals[8];
    float s = 0.f;
#pragma unroll
    for (int j = 0; j < 8; j++) {
        int i = threadIdx.x + (j << 8);
        float v = y[(size_t)r * DI + i];
        vals[j] = v;
        s += v;
    }
    float mean = block_sum(s, red) / (float)DI;
    float s2 = 0.f;
#pragma unroll
    for (int j = 0; j < 8; j++) { float d = vals[j] - mean; s2 += d * d; }
    float rstd = rsqrtf(block_sum(s2, red) / (float)DI + 1e-5f);
#pragma unroll
    for (int j = 0; j < 8; j++) {
        int i = threadIdx.x + (j << 8);
        float z = xz[(size_t)r * (2 * DI) + DI + i];
        float sz = z / (1.f + expf(-z));
        out[(size_t)r * DI + i] = ((vals[j] - mean) * rstd * gam[i] + bet[i]) * sz;
    }
}

// ---------------- depthwise conv1d k=3 pad=1 --------------------------------
__global__ void conv_kernel(const float* __restrict__ xz, const float* __restrict__ w,
                            const float* __restrict__ b, float* __restrict__ u) {
    int idx = blockIdx.x * blockDim.x + threadIdx.x;
    int c = idx & (DI - 1);
    int s = idx >> 11;
    float w0 = w[c * 3 + 0], w1 = w[c * 3 + 1], w2 = w[c * 3 + 2];
    float acc = b[c] + w1 * xz[(size_t)s * (2 * DI) + c];
    if (s > 0)     acc += w0 * xz[(size_t)(s - 1) * (2 * DI) + c];
    if (s < S - 1) acc += w2 * xz[(size_t)(s + 1) * (2 * DI) + c];
    u[(size_t)s * DI + c] = acc;
}

// ---------------- split-K reduction -----------------------------------------
__global__ void reduce_split_kernel(const float* __restrict__ part, float* __restrict__ out) {
    int i = blockIdx.x * blockDim.x + threadIdx.x;
    float s = 0.f;
#pragma unroll
    for (int z = 0; z < SPLITK; z++) s += part[(size_t)z * S * RB + i];
    out[i] = s;
}

// ---------------- fp32 -> bf16 hi/lo split ----------------------------------
__global__ void cvt_kernel(const float* __restrict__ src, int ld, int lcols,
                           __nv_bfloat16* __restrict__ hi, __nv_bfloat16* __restrict__ lo,
                           int total) {
    int idx = (blockIdx.x * blockDim.x + threadIdx.x) * 4;
    if (idx >= total) return;
    int r = idx >> lcols;
    int c = idx & ((1 << lcols) - 1);
    float4 v = *(const float4*)(src + (size_t)r * ld + c);
    __nv_bfloat16 h0 = __float2bfloat16(v.x), h1 = __float2bfloat16(v.y);
    __nv_bfloat16 h2 = __float2bfloat16(v.z), h3 = __float2bfloat16(v.w);
    __nv_bfloat16 l0 = __float2bfloat16(v.x - __bfloat162float(h0));
    __nv_bfloat16 l1 = __float2bfloat16(v.y - __bfloat162float(h1));
    __nv_bfloat16 l2 = __float2bfloat16(v.z - __bfloat162float(h2));
    __nv_bfloat16 l3 = __float2bfloat16(v.w - __bfloat162float(h3));
    __nv_bfloat162* H = (__nv_bfloat162*)(hi + idx);
    __nv_bfloat162* L = (__nv_bfloat162*)(lo + idx);
    H[0] = __halves2bfloat162(h0, h1);
    H[1] = __halves2bfloat162(h2, h3);
    L[0] = __halves2bfloat162(l0, l1);
    L[1] = __halves2bfloat162(l2, l3);
}

// ---------------- bf16 3-term mma.sync GEMM NT ------------------------------
// C[M,N] = A[M,K]*B[N,K]^T + ...   128x128x32 tile, 256 thr (8 warps 2x4),
// warp tile 64x32. hi/lo bf16 in gmem; cp.async 3-stage; ldmatrix SW64 swizzle.
#define STG_BYTES 32768      // 4 tiles x 8KB
#define T_AH 0
#define T_AL 8192
#define T_BH 16384
#define T_BL 24576
__global__ __launch_bounds__(256)
void gemm_mma(const __nv_bfloat16* __restrict__ Ahi, const __nv_bfloat16* __restrict__ Alo, int lda,
              const __nv_bfloat16* __restrict__ Bhi, const __nv_bfloat16* __restrict__ Blo, int ldb,
              const float* __restrict__ bias, const float* __restrict__ skip,
              float* __restrict__ C, int ldc, int N, int act, int kLen, size_t zstride) {
    extern __shared__ __align__(128) char smem[];
    const uint32_t sbase = (uint32_t)__cvta_generic_to_shared(smem);
    const int tid = threadIdx.x;
    const int lane = tid & 31;
    const int warp = tid >> 5;
    const int m0w = (warp >> 2) * 64;
    const int n0w = (warp & 3) * 32;
    const int bm = blockIdx.y * 128;
    const int bn = blockIdx.x * 128;
    const int kStart = blockIdx.z * kLen;
    float* Cz = C + (size_t)blockIdx.z * zstride;
    const int NC = kLen >> 5;      // K-chunks of 32

    float acc[4][4][4];
#pragma unroll
    for (int i = 0; i < 4; i++)
#pragma unroll
        for (int j = 0; j < 4; j++)
#pragma unroll
            for (int k = 0; k < 4; k++) acc[i][j][k] = 0.f;

    // ---- stage loader: 512 16B-slots per tensor tile ----
    auto load_stage = [&](int st, int c) {
        const int k0 = kStart + c * 32;
        uint32_t sb = sbase + st * STG_BYTES;
#pragma unroll
        for (int pass = 0; pass < 2; pass++) {
            int slot = tid + pass * 256;
            int row = slot >> 2;
            int ch = slot & 3;
            uint32_t so = (uint32_t)(row * 64 + ((ch ^ ((row >> 1) & 3)) << 4));
            const size_t aoff = (size_t)(bm + row) * lda + k0 + ch * 8;
            CP_ASYNC16(sb + T_AH + so, Ahi + aoff, 16);
            CP_ASYNC16(sb + T_AL + so, Alo + aoff, 16);
            int nrow = bn + row;
            int bsz = (nrow < N) ? 16 : 0;
            const size_t boff = (size_t)((nrow < N) ? nrow : 0) * ldb + k0 + ch * 8;
            CP_ASYNC16(sb + T_BH + so, Bhi + boff, bsz);
            CP_ASYNC16(sb + T_BL + so, Blo + boff, bsz);
        }
        CP_COMMIT();
    };

    int issued = 0;
    load_stage(0, 0); issued++;
    if (NC > 1) { load_stage(1, 1); issued++; }

    for (int c = 0; c < NC; c++) {
        if (c + 2 < NC) { load_stage((c + 2) % 3, c + 2); issued++; }
        int allow = issued - c - 1;
        if (allow >= 2)      { CP_WAIT(2); }
        else if (allow == 1) { CP_WAIT(1); }
        else                 { CP_WAIT(0); }
        __syncthreads();

        uint32_t sb = sbase + (c % 3) * STG_BYTES;
#pragma unroll
        for (int ka = 0; ka < 2; ka++) {
            uint32_t ah[4][4], al[4][4];
#pragma unroll
            for (int am = 0; am < 4; am++) {
                int row = m0w + am * 16 + (lane & 15);
                int ch = 2 * ka + (lane >> 4);
                uint32_t so = (uint32_t)(row * 64 + ((ch ^ ((row >> 1) & 3)) << 4));
                ldsm_x4(ah[am], sb + T_AH + so);
                ldsm_x4(al[am], sb + T_AL + so);
            }
            uint32_t bh[4][2], bl[4][2];
#pragma unroll
            for (int an = 0; an < 4; an++) {
                int row = n0w + an * 8 + (lane & 7);
                int ch = 2 * ka + ((lane >> 3) & 1);
                uint32_t so = (uint32_t)(row * 64 + ((ch ^ ((row >> 1) & 3)) << 4));
                ldsm_x2(bh[an], sb + T_BH + so);
                ldsm_x2(bl[an], sb + T_BL + so);
            }
#pragma unroll
            for (int am = 0; am < 4; am++)
#pragma unroll
                for (int an = 0; an < 4; an++) {
                    mma_bf16(acc[am][an], ah[am], bh[an]);
                    mma_bf16(acc[am][an], ah[am], bl[an]);
                    mma_bf16(acc[am][an], al[am], bh[an]);
                }
        }
        __syncthreads();
    }

    // ---- epilogue: direct global stores ----
    const int qr = lane >> 2;
    const int qc = (lane & 3) * 2;
#pragma unroll
    for (int am = 0; am < 4; am++) {
        int row0 = bm + m0w + am * 16 + qr;
        int row1 = row0 + 8;
#pragma unroll
        for (int an = 0; an < 4; an++) {
            int col = bn + n0w + an * 8 + qc;
            if (col < N) {
                float v0 = acc[am][an][0], v1 = acc[am][an][1];
                float v2 = acc[am][an][2], v3 = acc[am][an][3];
                if (bias) {
                    float b0 = bias[col], b1 = bias[col + 1];
                    v0 += b0; v1 += b1; v2 += b0; v3 += b1;
                }
                if (skip) {
                    v0 += skip[(size_t)row0 * ldc + col];
                    v1 += skip[(size_t)row0 * ldc + col + 1];
                    v2 += skip[(size_t)row1 * ldc + col];
                    v3 += skip[(size_t)row1 * ldc + col + 1];
                }
                if (act == 1) {
                    v0 = (v0 > 20.f) ? v0 : log1pf(expf(v0));
                    v1 = (v1 > 20.f) ? v1 : log1pf(expf(v1));
                    v2 = (v2 > 20.f) ? v2 : log1pf(expf(v2));
                    v3 = (v3 > 20.f) ? v3 : log1pf(expf(v3));
                }
                *(float2*)(Cz + (size_t)row0 * ldc + col) = make_float2(v0, v1);
                *(float2*)(Cz + (size_t)row1 * ldc + col) = make_float2(v2, v3);
            }
        }
    }
}

// ---------------- selective scan --------------------------------------------
__global__ void scan_kernel(const float* __restrict__ u, const float* __restrict__ delta,
                            const float* __restrict__ dbc, const float* __restrict__ A_log,
                            const float* __restrict__ Dp, float* __restrict__ y) {
    const int tid = threadIdx.x;
    const int nlane = tid & 15;
    const int dloc = tid >> 4;
    const int d = blockIdx.x * 16 + dloc;
    const float A = -__expf(A_log[d * NST + nlane]);
    const float Dv = Dp[d];
    float h = 0.f;
    for (int t = 0; t < S; t++) {
        float dt = delta[(size_t)t * DI + d];
        float uu = u[(size_t)t * DI + d];
        float Bn = dbc[(size_t)t * RB + 64 + nlane];
        float Cn = dbc[(size_t)t * RB + 80 + nlane];
        float dA = __expf(dt * A);
        h = dA * h + (dt * uu) * Bn;
        float p = h * Cn;
        p += __shfl_xor_sync(0xffffffffu, p, 1);
        p += __shfl_xor_sync(0xffffffffu, p, 2);
        p += __shfl_xor_sync(0xffffffffu, p, 4);
        p += __shfl_xor_sync(0xffffffffu, p, 8);
        if (nlane == 0) y[(size_t)t * DI + d] = p + Dv * uu;
    }
}

// ---------------- launcher ---------------------------------------------------
extern "C" void kernel_launch(void* const* d_in, const int* in_sizes, int n_in,
                              void* d_out, int out_size) {
    const float* x         = (const float*)d_in[0];
    const float* pos_enc   = (const float*)d_in[1];
    const float* ln_g      = (const float*)d_in[2];
    const float* ln_b      = (const float*)d_in[3];
    const float* innorm_g  = (const float*)d_in[4];
    const float* innorm_b  = (const float*)d_in[5];
    const float* in_proj_w = (const float*)d_in[6];
    const float* in_proj_b = (const float*)d_in[7];
    const float* conv_w    = (const float*)d_in[8];
    const float* conv_b    = (const float*)d_in[9];
    const float* deltaBC_w = (const float*)d_in[10];
    const float* dt_proj_w = (const float*)d_in[11];
    const float* dt_proj_b = (const float*)d_in[12];
    const float* A_log     = (const float*)d_in[13];
    const float* Dp        = (const float*)d_in[14];
    const float* outnorm_g = (const float*)d_in[15];
    const float* outnorm_b = (const float*)d_in[16];
    const float* out_proj_w= (const float*)d_in[17];
    const float* out_proj_b= (const float*)d_in[18];

    float *enc, *h, *xz, *u, *dbc, *delta, *y, *gated, *split;
    __nv_bfloat16 *ahi, *alo, *bhi, *blo;
    cudaGetSymbolAddress((void**)&enc,   g_enc);
    cudaGetSymbolAddress((void**)&h,     g_h);
    cudaGetSymbolAddress((void**)&xz,    g_xz);
    cudaGetSymbolAddress((void**)&u,     g_u);
    cudaGetSymbolAddress((void**)&dbc,   g_dbc);
    cudaGetSymbolAddress((void**)&delta, g_delta);
    cudaGetSymbolAddress((void**)&y,     g_y);
    cudaGetSymbolAddress((void**)&gated, g_gated);
    cudaGetSymbolAddress((void**)&split, g_split);
    cudaGetSymbolAddress((void**)&ahi,   g_ahi);
    cudaGetSymbolAddress((void**)&alo,   g_alo);
    cudaGetSymbolAddress((void**)&bhi,   g_bhi);
    cudaGetSymbolAddress((void**)&blo,   g_blo);

    const int SMEM_G = 3 * STG_BYTES;    // 96 KB
    static int attr_done = 0;
    if (!attr_done) {
        cudaFuncSetAttribute(gemm_mma, cudaFuncAttributeMaxDynamicSharedMemorySize, SMEM_G);
        attr_done = 1;
    }

    // enc = LN(x + pos_enc)
    ln_kernel<<<S, 256>>>(x, pos_enc, ln_g, ln_b, enc, DM, 1e-6f);

    for (int i = 0; i < 4; i++) {
        // h = LN(enc)
        ln_kernel<<<S, 256>>>(enc, nullptr, innorm_g + i * DM, innorm_b + i * DM, h, DM, 1e-5f);
        // convert h, in_proj_w
        cvt_kernel<<<(S * DM) / 1024, 256>>>(h, DM, 10, ahi, alo, S * DM);
        cvt_kernel<<<(2 * DI * DM) / 1024, 256>>>(in_proj_w + (size_t)i * 2 * DI * DM, DM, 10,
                                                  bhi, blo, 2 * DI * DM);
        // xz = h @ in_proj_w^T + b   [4096, 4096] K=1024
        gemm_mma<<<dim3(32, 32, 1), 256, SMEM_G>>>(ahi, alo, DM, bhi, blo, DM,
                                                   in_proj_b + (size_t)i * 2 * DI, nullptr,
                                                   xz, 2 * DI, 2 * DI, 0, DM, 0);
        // u = depthwise conv(x1)
        conv_kernel<<<(S * DI) / 256, 256>>>(xz, conv_w + (size_t)i * DI * 3,
                                             conv_b + (size_t)i * DI, u);
        // convert u, deltaBC_w
        cvt_kernel<<<(S * DI) / 1024, 256>>>(u, DI, 11, ahi, alo, S * DI);
        cvt_kernel<<<(RB * DI) / 1024, 256>>>(deltaBC_w + (size_t)i * RB * DI, DI, 11,
                                              bhi, blo, RB * DI);
        // dbc = u @ deltaBC_w^T   [4096, 96], K=2048 split-K=4
        gemm_mma<<<dim3(1, 32, SPLITK), 256, SMEM_G>>>(ahi, alo, DI, bhi, blo, DI,
                                                       nullptr, nullptr, split, RB, RB, 0,
                                                       DI / SPLITK, (size_t)S * RB);
        reduce_split_kernel<<<(S * RB) / 256, 256>>>(split, dbc);
        // convert dbc[:, :64], dt_proj_w
        cvt_kernel<<<(S * 64) / 1024, 256>>>(dbc, RB, 6, ahi, alo, S * 64);
        cvt_kernel<<<(DI * 64) / 1024, 256>>>(dt_proj_w + (size_t)i * DI * 64, 64, 6,
                                              bhi, blo, DI * 64);
        // delta = softplus(dbc64 @ dt_proj_w^T + b)   [4096, 2048] K=64
        gemm_mma<<<dim3(16, 32, 1), 256, SMEM_G>>>(ahi, alo, 64, bhi, blo, 64,
                                                   dt_proj_b + (size_t)i * DI, nullptr,
                                                   delta, DI, DI, 1, 64, 0);
        // selective scan
        scan_kernel<<<DI / 16, 256>>>(u, delta, dbc, A_log + (size_t)i * DI * NST,
                                      Dp + (size_t)i * DI, y);
        // gated = LN(y) * silu(z1)
        ln_gate_kernel<<<S, 256>>>(y, xz, outnorm_g + (size_t)i * DI,
                                   outnorm_b + (size_t)i * DI, gated);
        // convert gated, out_proj_w
        cvt_kernel<<<(S * DI) / 1024, 256>>>(gated, DI, 11, ahi, alo, S * DI);
        cvt_kernel<<<(DM * DI) / 1024, 256>>>(out_proj_w + (size_t)i * DM * DI, DI, 11,
                                              bhi, blo, DM * DI);
        // enc = gated @ out_proj_w^T + b + enc   [4096, 1024] K=2048
        float* dest = (i == 3) ? (float*)d_out : enc;
        gemm_mma<<<dim3(8, 32, 1), 256, SMEM_G>>>(ahi, alo, DI, bhi, blo, DI,
                                                  out_proj_b + (size_t)i * DM, enc,
                                                  dest, DM, DM, 0, DI, 0);
    }
}

// round 5
// speedup vs baseline: 1.8243x; 1.0822x over previous
#include <cuda_runtime.h>
#include <cuda_fp16.h>
#include <math.h>
#include <stdint.h>

#define S    4096
#define DM   1024
#define DI   2048
#define NST  16
#define RB   96
#define SPLITK 4

// ---------------- scratch (device globals) ---------------------------------
__device__ float g_enc[S * DM];
__device__ float g_xz[S * 2 * DI];
__device__ float g_u[S * DI];
__device__ float g_dbc[S * RB];
__device__ float g_delta[S * DI];
__device__ float g_y[S * DI];
__device__ float g_split[SPLITK * S * RB];
__device__ __half g_ahi[S * DI];
__device__ __half g_alo[S * DI];
__device__ __half g_w16[2 * DI * DM];

// ---------------- PTX helpers ----------------------------------------------
__device__ __forceinline__ void mma_f16(float* d, const uint32_t* a, const uint32_t* b) {
    asm volatile("mma.sync.aligned.m16n8k16.row.col.f32.f16.f16.f32 "
        "{%0,%1,%2,%3},{%4,%5,%6,%7},{%8,%9},{%0,%1,%2,%3};"
        : "+f"(d[0]), "+f"(d[1]), "+f"(d[2]), "+f"(d[3])
        : "r"(a[0]), "r"(a[1]), "r"(a[2]), "r"(a[3]), "r"(b[0]), "r"(b[1]));
}
__device__ __forceinline__ void ldsm_x4(uint32_t* r, uint32_t addr) {
    asm volatile("ldmatrix.sync.aligned.m8n8.x4.shared.b16 {%0,%1,%2,%3}, [%4];"
        : "=r"(r[0]), "=r"(r[1]), "=r"(r[2]), "=r"(r[3]) : "r"(addr));
}
__device__ __forceinline__ void ldsm_x2(uint32_t* r, uint32_t addr) {
    asm volatile("ldmatrix.sync.aligned.m8n8.x2.shared.b16 {%0,%1}, [%2];"
        : "=r"(r[0]), "=r"(r[1]) : "r"(addr));
}
#define CP_ASYNC16(dst, src, sz) \
    asm volatile("cp.async.cg.shared.global [%0], [%1], 16, %2;" \
                 :: "r"(dst), "l"(src), "r"(sz) : "memory")
#define CP_COMMIT() asm volatile("cp.async.commit_group;" ::: "memory")
#define CP_WAIT(n)  asm volatile("cp.async.wait_group %0;" :: "n"(n) : "memory")

// ---------------- hi/lo fp16 split -----------------------------------------
__device__ __forceinline__ void split16(float a, __half& hi, __half& lo) {
    hi = __float2half_rn(a);
    lo = __float2half_rn(a - __half2float(hi));
}

// ---------------- block reduction helper ------------------------------------
__device__ __forceinline__ float block_sum(float v, float* red) {
#pragma unroll
    for (int o = 16; o; o >>= 1) v += __shfl_xor_sync(0xffffffffu, v, o);
    if ((threadIdx.x & 31) == 0) red[threadIdx.x >> 5] = v;
    __syncthreads();
    float t = red[0] + red[1] + red[2] + red[3] + red[4] + red[5] + red[6] + red[7];
    __syncthreads();
    return t;
}

// ---------------- LayerNorm -> fp32 (first LN only) --------------------------
__global__ void ln_kernel(const float* __restrict__ src, const float* __restrict__ add,
                          const float* __restrict__ gam, const float* __restrict__ bet,
                          float* __restrict__ out, int W, float eps) {
    __shared__ float red[8];
    const int r = blockIdx.x;
    const int nloc = W >> 8;
    float vals[8];
    float s = 0.f;
    for (int j = 0; j < nloc; j++) {
        int i = threadIdx.x + (j << 8);
        float v = src[(size_t)r * W + i];
        if (add) v += add[(size_t)r * W + i];
        vals[j] = v;
        s += v;
    }
    float mean = block_sum(s, red) / (float)W;
    float s2 = 0.f;
    for (int j = 0; j < nloc; j++) { float d = vals[j] - mean; s2 += d * d; }
    float rstd = rsqrtf(block_sum(s2, red) / (float)W + eps);
    for (int j = 0; j < nloc; j++) {
        int i = threadIdx.x + (j << 8);
        out[(size_t)r * W + i] = (vals[j] - mean) * rstd * gam[i] + bet[i];
    }
}

// ---------------- LayerNorm -> fp16 hi/lo (W = 1024) -------------------------
__global__ void ln_h16_kernel(const float* __restrict__ src,
                              const float* __restrict__ gam, const float* __restrict__ bet,
                              __half* __restrict__ hi, __half* __restrict__ lo) {
    __shared__ float red[8];
    const int r = blockIdx.x;
    float vals[4];
    float s = 0.f;
#pragma unroll
    for (int j = 0; j < 4; j++) {
        int i = threadIdx.x + (j << 8);
        float v = src[(size_t)r * DM + i];
        vals[j] = v;
        s += v;
    }
    float mean = block_sum(s, red) / (float)DM;
    float s2 = 0.f;
#pragma unroll
    for (int j = 0; j < 4; j++) { float d = vals[j] - mean; s2 += d * d; }
    float rstd = rsqrtf(block_sum(s2, red) / (float)DM + 1e-5f);
#pragma unroll
    for (int j = 0; j < 4; j++) {
        int i = threadIdx.x + (j << 8);
        float v = (vals[j] - mean) * rstd * gam[i] + bet[i];
        __half h, l;
        split16(v, h, l);
        hi[(size_t)r * DM + i] = h;
        lo[(size_t)r * DM + i] = l;
    }
}

// ---------------- LN(y)*silu(z) -> fp16 hi/lo (W = 2048) ---------------------
__global__ void ln_gate_kernel(const float* __restrict__ y, const float* __restrict__ xz,
                               const float* __restrict__ gam, const float* __restrict__ bet,
                               __half* __restrict__ hi, __half* __restrict__ lo) {
    __shared__ float red[8];
    const int r = blockIdx.x;
    float vals[8];
    float s = 0.f;
#pragma unroll
    for (int j = 0; j < 8; j++) {
        int i = threadIdx.x + (j << 8);
        float v = y[(size_t)r * DI + i];
        vals[j] = v;
        s += v;
    }
    float mean = block_sum(s, red) / (float)DI;
    float s2 = 0.f;
#pragma unroll
    for (int j = 0; j < 8; j++) { float d = vals[j] - mean; s2 += d * d; }
    float rstd = rsqrtf(block_sum(s2, red) / (float)DI + 1e-5f);
#pragma unroll
    for (int j = 0; j < 8; j++) {
        int i = threadIdx.x + (j << 8);
        float z = xz[(size_t)r * (2 * DI) + DI + i];
        float sz = z / (1.f + expf(-z));
        float v = ((vals[j] - mean) * rstd * gam[i] + bet[i]) * sz;
        __half h, l;
        split16(v, h, l);
        hi[(size_t)r * DI + i] = h;
        lo[(size_t)r * DI + i] = l;
    }
}

// ---------------- depthwise conv1d k=3 pad=1 (+ hi/lo out) ------------------
__global__ void conv_kernel(const float* __restrict__ xz, const float* __restrict__ w,
                            const float* __restrict__ b, float* __restrict__ u,
                            __half* __restrict__ hi, __half* __restrict__ lo) {
    int idx = blockIdx.x * blockDim.x + threadIdx.x;
    int c = idx & (DI - 1);
    int s = idx >> 11;
    float w0 = w[c * 3 + 0], w1 = w[c * 3 + 1], w2 = w[c * 3 + 2];
    float acc = b[c] + w1 * xz[(size_t)s * (2 * DI) + c];
    if (s > 0)     acc += w0 * xz[(size_t)(s - 1) * (2 * DI) + c];
    if (s < S - 1) acc += w2 * xz[(size_t)(s + 1) * (2 * DI) + c];
    u[idx] = acc;
    __half h, l;
    split16(acc, h, l);
    hi[idx] = h;
    lo[idx] = l;
}

// ---------------- split-K reduction (+ hi/lo of first 64 cols) --------------
__global__ void reduce_split_kernel(const float* __restrict__ part, float* __restrict__ out,
                                    __half* __restrict__ hi, __half* __restrict__ lo) {
    int i = blockIdx.x * blockDim.x + threadIdx.x;
    float s = 0.f;
#pragma unroll
    for (int z = 0; z < SPLITK; z++) s += part[(size_t)z * S * RB + i];
    out[i] = s;
    int r = i / RB, c = i - r * RB;
    if (c < 64) {
        __half h, l;
        split16(s, h, l);
        hi[r * 64 + c] = h;
        lo[r * 64 + c] = l;
    }
}

// ---------------- weight fp32 -> fp16 ---------------------------------------
__global__ void wcvt_kernel(const float* __restrict__ src, __half* __restrict__ dst, int total) {
    int idx = (blockIdx.x * blockDim.x + threadIdx.x) * 4;
    if (idx >= total) return;
    float4 v = *(const float4*)(src + idx);
    __half2* D = (__half2*)(dst + idx);
    D[0] = __halves2half2(__float2half_rn(v.x), __float2half_rn(v.y));
    D[1] = __halves2half2(__float2half_rn(v.z), __float2half_rn(v.w));
}

// ---------------- fp16 2-term mma GEMM NT -----------------------------------
// C[M,N] = (Ahi+Alo)[M,K] * B16[N,K]^T   128x128x32 tile, 256 thr (8 warps 2x4),
// warp tile 64x32. 4-stage cp.async, one __syncthreads per chunk, SW64 swizzle.
#define STG_BYTES 24576      // ahi 8KB + alo 8KB + b 8KB
#define T_AH 0
#define T_AL 8192
#define T_BH 16384
__global__ __launch_bounds__(256)
void gemm_mma(const __half* __restrict__ Ahi, const __half* __restrict__ Alo, int lda,
              const __half* __restrict__ B16, int ldb,
              const float* __restrict__ bias, const float* __restrict__ skip,
              float* __restrict__ C, int ldc, int N, int act, int kLen, size_t zstride) {
    extern __shared__ __align__(128) char smem[];
    const uint32_t sbase = (uint32_t)__cvta_generic_to_shared(smem);
    const int tid = threadIdx.x;
    const int lane = tid & 31;
    const int warp = tid >> 5;
    const int m0w = (warp >> 2) * 64;
    const int n0w = (warp & 3) * 32;
    const int bm = blockIdx.y * 128;
    const int bn = blockIdx.x * 128;
    const int kStart = blockIdx.z * kLen;
    float* Cz = C + (size_t)blockIdx.z * zstride;
    const int NC = kLen >> 5;

    float acc[4][4][4];
#pragma unroll
    for (int i = 0; i < 4; i++)
#pragma unroll
        for (int j = 0; j < 4; j++)
#pragma unroll
            for (int k = 0; k < 4; k++) acc[i][j][k] = 0.f;

    auto load_stage = [&](int st, int c) {
        const int k0 = kStart + c * 32;
        uint32_t sb = sbase + st * STG_BYTES;
#pragma unroll
        for (int j = 0; j < 6; j++) {
            int sl = tid + (j & 1) * 256;          // 0..511
            int row = sl >> 2;
            int ch = sl & 3;
            uint32_t so = (uint32_t)(row * 64 + ((ch ^ ((row >> 1) & 3)) << 4));
            if (j < 2) {
                CP_ASYNC16(sb + T_AH + so, Ahi + (size_t)(bm + row) * lda + k0 + ch * 8, 16);
            } else if (j < 4) {
                CP_ASYNC16(sb + T_AL + so, Alo + (size_t)(bm + row) * lda + k0 + ch * 8, 16);
            } else {
                int nrow = bn + row;
                int bsz = (nrow < N) ? 16 : 0;
                CP_ASYNC16(sb + T_BH + so,
                           B16 + (size_t)((nrow < N) ? nrow : 0) * ldb + k0 + ch * 8, bsz);
            }
        }
        CP_COMMIT();
    };

    int issued = 0;
    for (int p = 0; p < 3 && p < NC; p++) { load_stage(p, p); issued++; }

    for (int c = 0; c < NC; c++) {
        int allow = issued - c - 1;
        if (allow >= 2)      { CP_WAIT(2); }
        else if (allow == 1) { CP_WAIT(1); }
        else                 { CP_WAIT(0); }
        __syncthreads();
        if (c + 3 < NC) { load_stage((c + 3) & 3, c + 3); issued++; }

        uint32_t sb = sbase + (c & 3) * STG_BYTES;
#pragma unroll
        for (int ka = 0; ka < 2; ka++) {
            uint32_t ah[4][4], al[4][4];
#pragma unroll
            for (int am = 0; am < 4; am++) {
                int row = m0w + am * 16 + (lane & 15);
                int ch = 2 * ka + (lane >> 4);
                uint32_t so = (uint32_t)(row * 64 + ((ch ^ ((row >> 1) & 3)) << 4));
                ldsm_x4(ah[am], sb + T_AH + so);
                ldsm_x4(al[am], sb + T_AL + so);
            }
            uint32_t bh[4][2];
#pragma unroll
            for (int an = 0; an < 4; an++) {
                int row = n0w + an * 8 + (lane & 7);
                int ch = 2 * ka + ((lane >> 3) & 1);
                uint32_t so = (uint32_t)(row * 64 + ((ch ^ ((row >> 1) & 3)) << 4));
                ldsm_x2(bh[an], sb + T_BH + so);
            }
#pragma unroll
            for (int am = 0; am < 4; am++)
#pragma unroll
                for (int an = 0; an < 4; an++) {
                    mma_f16(acc[am][an], ah[am], bh[an]);
                    mma_f16(acc[am][an], al[am], bh[an]);
                }
        }
        __syncthreads();
    }

    // ---- epilogue: direct global stores ----
    const int qr = lane >> 2;
    const int qc = (lane & 3) * 2;
#pragma unroll
    for (int am = 0; am < 4; am++) {
        int row0 = bm + m0w + am * 16 + qr;
        int row1 = row0 + 8;
#pragma unroll
        for (int an = 0; an < 4; an++) {
            int col = bn + n0w + an * 8 + qc;
            if (col < N) {
                float v0 = acc[am][an][0], v1 = acc[am][an][1];
                float v2 = acc[am][an][2], v3 = acc[am][an][3];
                if (bias) {
                    float b0 = bias[col], b1 = bias[col + 1];
                    v0 += b0; v1 += b1; v2 += b0; v3 += b1;
                }
                if (skip) {
                    v0 += skip[(size_t)row0 * ldc + col];
                    v1 += skip[(size_t)row0 * ldc + col + 1];
                    v2 += skip[(size_t)row1 * ldc + col];
                    v3 += skip[(size_t)row1 * ldc + col + 1];
                }
                if (act == 1) {
                    v0 = (v0 > 20.f) ? v0 : log1pf(expf(v0));
                    v1 = (v1 > 20.f) ? v1 : log1pf(expf(v1));
                    v2 = (v2 > 20.f) ? v2 : log1pf(expf(v2));
                    v3 = (v3 > 20.f) ? v3 : log1pf(expf(v3));
                }
                *(float2*)(Cz + (size_t)row0 * ldc + col) = make_float2(v0, v1);
                *(float2*)(Cz + (size_t)row1 * ldc + col) = make_float2(v2, v3);
            }
        }
    }
}

// ---------------- selective scan --------------------------------------------
__global__ void scan_kernel(const float* __restrict__ u, const float* __restrict__ delta,
                            const float* __restrict__ dbc, const float* __restrict__ A_log,
                            const float* __restrict__ Dp, float* __restrict__ y) {
    const int tid = threadIdx.x;
    const int nlane = tid & 15;
    const int dloc = tid >> 4;
    const int d = blockIdx.x * 16 + dloc;
    const float A = -__expf(A_log[d * NST + nlane]);
    const float Dv = Dp[d];
    float h = 0.f;
    for (int t = 0; t < S; t++) {
        float dt = delta[(size_t)t * DI + d];
        float uu = u[(size_t)t * DI + d];
        float Bn = dbc[(size_t)t * RB + 64 + nlane];
        float Cn = dbc[(size_t)t * RB + 80 + nlane];
        float dA = __expf(dt * A);
        h = dA * h + (dt * uu) * Bn;
        float p = h * Cn;
        p += __shfl_xor_sync(0xffffffffu, p, 1);
        p += __shfl_xor_sync(0xffffffffu, p, 2);
        p += __shfl_xor_sync(0xffffffffu, p, 4);
        p += __shfl_xor_sync(0xffffffffu, p, 8);
        if (nlane == 0) y[(size_t)t * DI + d] = p + Dv * uu;
    }
}

// ---------------- launcher ---------------------------------------------------
extern "C" void kernel_launch(void* const* d_in, const int* in_sizes, int n_in,
                              void* d_out, int out_size) {
    const float* x         = (const float*)d_in[0];
    const float* pos_enc   = (const float*)d_in[1];
    const float* ln_g      = (const float*)d_in[2];
    const float* ln_b      = (const float*)d_in[3];
    const float* innorm_g  = (const float*)d_in[4];
    const float* innorm_b  = (const float*)d_in[5];
    const float* in_proj_w = (const float*)d_in[6];
    const float* in_proj_b = (const float*)d_in[7];
    const float* conv_w    = (const float*)d_in[8];
    const float* conv_b    = (const float*)d_in[9];
    const float* deltaBC_w = (const float*)d_in[10];
    const float* dt_proj_w = (const float*)d_in[11];
    const float* dt_proj_b = (const float*)d_in[12];
    const float* A_log     = (const float*)d_in[13];
    const float* Dp        = (const float*)d_in[14];
    const float* outnorm_g = (const float*)d_in[15];
    const float* outnorm_b = (const float*)d_in[16];
    const float* out_proj_w= (const float*)d_in[17];
    const float* out_proj_b= (const float*)d_in[18];

    float *enc, *xz, *u, *dbc, *delta, *y, *split;
    __half *ahi, *alo, *w16;
    cudaGetSymbolAddress((void**)&enc,   g_enc);
    cudaGetSymbolAddress((void**)&xz,    g_xz);
    cudaGetSymbolAddress((void**)&u,     g_u);
    cudaGetSymbolAddress((void**)&dbc,   g_dbc);
    cudaGetSymbolAddress((void**)&delta, g_delta);
    cudaGetSymbolAddress((void**)&y,     g_y);
    cudaGetSymbolAddress((void**)&split, g_split);
    cudaGetSymbolAddress((void**)&ahi,   g_ahi);
    cudaGetSymbolAddress((void**)&alo,   g_alo);
    cudaGetSymbolAddress((void**)&w16,   g_w16);

    const int SMEM_G = 4 * STG_BYTES;    // 96 KB
    static int attr_done = 0;
    if (!attr_done) {
        cudaFuncSetAttribute(gemm_mma, cudaFuncAttributeMaxDynamicSharedMemorySize, SMEM_G);
        attr_done = 1;
    }

    // enc = LN(x + pos_enc)
    ln_kernel<<<S, 256>>>(x, pos_enc, ln_g, ln_b, enc, DM, 1e-6f);

    for (int i = 0; i < 4; i++) {
        // h = LN(enc) -> fp16 hi/lo
        ln_h16_kernel<<<S, 256>>>(enc, innorm_g + i * DM, innorm_b + i * DM, ahi, alo);
        wcvt_kernel<<<(2 * DI * DM) / 1024, 256>>>(in_proj_w + (size_t)i * 2 * DI * DM,
                                                   w16, 2 * DI * DM);
        // xz = h @ in_proj_w^T + b   [4096, 4096] K=1024
        gemm_mma<<<dim3(32, 32, 1), 256, SMEM_G>>>(ahi, alo, DM, w16, DM,
                                                   in_proj_b + (size_t)i * 2 * DI, nullptr,
                                                   xz, 2 * DI, 2 * DI, 0, DM, 0);
        // u = depthwise conv(x1) -> fp32 + fp16 hi/lo
        conv_kernel<<<(S * DI) / 256, 256>>>(xz, conv_w + (size_t)i * DI * 3,
                                             conv_b + (size_t)i * DI, u, ahi, alo);
        wcvt_kernel<<<(RB * DI) / 1024, 256>>>(deltaBC_w + (size_t)i * RB * DI, w16, RB * DI);
        // dbc = u @ deltaBC_w^T   [4096, 96], K=2048 split-K=4
        gemm_mma<<<dim3(1, 32, SPLITK), 256, SMEM_G>>>(ahi, alo, DI, w16, DI,
                                                       nullptr, nullptr, split, RB, RB, 0,
                                                       DI / SPLITK, (size_t)S * RB);
        reduce_split_kernel<<<(S * RB) / 256, 256>>>(split, dbc, ahi, alo);
        wcvt_kernel<<<(DI * 64) / 1024, 256>>>(dt_proj_w + (size_t)i * DI * 64, w16, DI * 64);
        // delta = softplus(dbc64 @ dt_proj_w^T + b)   [4096, 2048] K=64
        gemm_mma<<<dim3(16, 32, 1), 256, SMEM_G>>>(ahi, alo, 64, w16, 64,
                                                   dt_proj_b + (size_t)i * DI, nullptr,
                                                   delta, DI, DI, 1, 64, 0);
        // selective scan
        scan_kernel<<<DI / 16, 256>>>(u, delta, dbc, A_log + (size_t)i * DI * NST,
                                      Dp + (size_t)i * DI, y);
        // gated = LN(y) * silu(z1) -> fp16 hi/lo
        ln_gate_kernel<<<S, 256>>>(y, xz, outnorm_g + (size_t)i * DI,
                                   outnorm_b + (size_t)i * DI, ahi, alo);
        wcvt_kernel<<<(DM * DI) / 1024, 256>>>(out_proj_w + (size_t)i * DM * DI, w16, DM * DI);
        // enc = gated @ out_proj_w^T + b + enc   [4096, 1024] K=2048
        float* dest = (i == 3) ? (float*)d_out : enc;
        gemm_mma<<<dim3(8, 32, 1), 256, SMEM_G>>>(ahi, alo, DI, w16, DI,
                                                  out_proj_b + (size_t)i * DM, enc,
                                                  dest, DM, DM, 0, DI, 0);
    }
}